// round 6
// baseline (speedup 1.0000x reference)
#include <cuda_runtime.h>
#include <cstdint>

// high_order_input: x[4,8,128,128] f32 -> out[4,8,210,16384] f32
// ht2: 45 pairs c_i*c_j (i<=j); ht3: 165 triples c_i*c_j*c_k (i<=j<=k), matching
// reference tpcm2/tpcm3 enumeration order (verified rel_err 3.9e-08 in R1-R5).
//
// R6: TERM-MAJOR decomposition. Pixel-major variants plateaued at 72-75us /
// ~6.0 TB/s writes regardless of occupancy or store width -> backend-limited.
// Hypothesis: 210-way 64KB-strided write interleave thrashes DRAM row buffers.
// Here one CTA = one (plane, term) and writes a single contiguous 64KB stream.
// Input plane (64KB) stays L1-resident; shifted operand vectors come from one
// coalesced float4 row load per lane + __shfl for the +-1 pixel shifts.

#define HWDIM 128
#define LPIX  (HWDIM * HWDIM)   // 16384
#define NTERM 210
#define FULLM 0xffffffffu

// Shift a warp-distributed row vector (lane holds pixels 4L..4L+3) by c-1 pixels:
// c=0 -> left neighbor (w-1, zero pad), c=1 -> centered, c=2 -> right neighbor.
// Branches are warp-uniform (c is CTA-uniform), so the shfls are convergent.
__device__ __forceinline__ float4 shifted(float4 v, int c, int lane)
{
    if (c == 1) return v;
    if (c == 0) {
        float pw = __shfl_up_sync(FULLM, v.w, 1);
        return make_float4(lane == 0 ? 0.f : pw, v.x, v.y, v.z);
    }
    float nx = __shfl_down_sync(FULLM, v.x, 1);
    return make_float4(v.y, v.z, v.w, lane == 31 ? 0.f : nx);
}

__global__ __launch_bounds__(256, 8)
void high_order_term_kernel(const float* __restrict__ x, float* __restrict__ out)
{
    const int cta = blockIdx.x;          // 0 .. 32*210-1
    const int p   = cta / NTERM;         // plane
    const int t   = cta - p * NTERM;     // term index 0..209

    // Decode term t -> offsets (ti, tj, tk); tk = -1 for order-2 terms.
    // Enumeration: t2 = 0..44 (i-major, j>=i); t3 = 45..209 (i-major, j>=i, k>=j).
    int ti = 0, tj = 0, tk = -1;
    {
        bool found = false;
        if (t < 45) {
            int c = 0;
            for (int i = 0; i < 9 && !found; i++)
                for (int j = i; j < 9 && !found; j++) {
                    if (c == t) { ti = i; tj = j; found = true; }
                    c++;
                }
        } else {
            int c = 45;
            for (int i = 0; i < 9 && !found; i++)
                for (int j = i; j < 9 && !found; j++)
                    for (int k = j; k < 9 && !found; k++) {
                        if (c == t) { ti = i; tj = j; tk = k; found = true; }
                        c++;
                    }
        }
    }
    const int di = ti / 3, ci = ti % 3;
    const int dj = tj / 3, cj = tj % 3;
    const int dk = (tk >= 0) ? tk / 3 : 1;
    const int ck = (tk >= 0) ? tk % 3 : 1;

    const int lane = threadIdx.x & 31;
    const int warp = threadIdx.x >> 5;

    const float* __restrict__ xp = x + (size_t)p * LPIX;
    float* __restrict__ op = out + ((size_t)p * NTERM + t) * LPIX;

    // Each warp handles 16 consecutive rows; lane L covers pixels 4L..4L+3.
    #pragma unroll 4
    for (int it = 0; it < 16; it++) {
        const int h = warp * 16 + it;

        // Rows h-1, h, h+1, zero-padded; one coalesced float4 per lane per row.
        const int base = h * HWDIM + 4 * lane;
        float4 r0 = (h > 0)
            ? __ldg(reinterpret_cast<const float4*>(xp + base - HWDIM))
            : make_float4(0.f, 0.f, 0.f, 0.f);
        float4 r1 = __ldg(reinterpret_cast<const float4*>(xp + base));
        float4 r2 = (h < HWDIM - 1)
            ? __ldg(reinterpret_cast<const float4*>(xp + base + HWDIM))
            : make_float4(0.f, 0.f, 0.f, 0.f);

        // Select row by CTA-uniform dr (SEL chains, stays in registers).
        float4 vi = (di == 0) ? r0 : (di == 1) ? r1 : r2;
        float4 vj = (dj == 0) ? r0 : (dj == 1) ? r1 : r2;
        vi = shifted(vi, ci, lane);
        vj = shifted(vj, cj, lane);

        float4 prod;
        prod.x = vi.x * vj.x;
        prod.y = vi.y * vj.y;
        prod.z = vi.z * vj.z;
        prod.w = vi.w * vj.w;

        if (tk >= 0) {
            float4 vk = (dk == 0) ? r0 : (dk == 1) ? r1 : r2;
            vk = shifted(vk, ck, lane);
            prod.x *= vk.x;
            prod.y *= vk.y;
            prod.z *= vk.z;
            prod.w *= vk.w;
        }

        __stcs(reinterpret_cast<float4*>(op + base), prod);
    }
}

extern "C" void kernel_launch(void* const* d_in, const int* in_sizes, int n_in,
                              void* d_out, int out_size)
{
    const float* x = (const float*)d_in[0];
    float* out = (float*)d_out;
    // tpcm2 (d_in[1]) / tpcm3 (d_in[2]) are compile-time constants for K=3; hardcoded.
    (void)in_sizes; (void)n_in; (void)out_size;

    const int grid = 32 * NTERM;   // one CTA per (plane, term) = 6720 CTAs
    const int block = 256;         // 8 warps x 16 rows = 128 rows
    high_order_term_kernel<<<grid, block>>>(x, out);
}

// round 7
// speedup vs baseline: 1.8425x; 1.8425x over previous
#include <cuda_runtime.h>
#include <cstdint>

// high_order_input: x[4,8,128,128] f32 -> out[4,8,210,16384] f32
// ht2: 45 pairs c_i*c_j (i<=j); ht3: 165 triples c_i*c_j*c_k (i<=j<=k), matching
// reference tpcm2/tpcm3 order (verified rel_err 3.9e-08 across R1-R6).
//
// R7: term-major (1 CTA = 1 (plane,term), contiguous 64KB write stream) with the
// R6 SM-side overheads removed: arithmetic term decode (~120 instrs, was ~1000+),
// compile-time row selection via 10/6 template specializations (was SEL chains),
// rolling 3-row register window (1 row load/iter, was 3). Budget: ~24us issue,
// ~26us L1 — DRAM is the only limiter left, so this cleanly tests whether
// sequential-stream writes beat the 210-way strided interleave (~67% of peak).

#define HWDIM 128
#define LPIX  (HWDIM * HWDIM)   // 16384
#define NTERM 210
#define FULLM 0xffffffffu

__device__ __forceinline__ float4 zero4() { return make_float4(0.f, 0.f, 0.f, 0.f); }

// Horizontal shift of a warp-distributed row (lane L holds cols 4L..4L+3).
// c=0 -> cols w-1 (zero pad at col -1), c=1 -> centered, c=2 -> cols w+1 (pad at 128).
// c is CTA-uniform -> branches are convergent.
__device__ __forceinline__ float4 hshift(float4 v, int c, int lane)
{
    if (c == 1) return v;
    if (c == 0) {
        float pw = __shfl_up_sync(FULLM, v.w, 1);
        return make_float4(lane == 0 ? 0.f : pw, v.x, v.y, v.z);
    }
    float nx = __shfl_down_sync(FULLM, v.x, 1);
    return make_float4(v.y, v.z, v.w, lane == 31 ? 0.f : nx);
}

template <int DI, int DJ, int DK, bool TRIPLE>
__device__ __forceinline__ void run_term(const float* __restrict__ xp,
                                         float* __restrict__ op,
                                         int ci, int cj, int ck,
                                         int lane, int warp)
{
    const int h0   = warp * 16;
    const int colb = 4 * lane;

    // Rolling window: rm = row h-1, rc = row h, rp = row h+1 (zero outside).
    float4 rm = (h0 > 0) ? __ldg(reinterpret_cast<const float4*>(xp + (h0 - 1) * HWDIM + colb))
                         : zero4();
    float4 rc = __ldg(reinterpret_cast<const float4*>(xp + h0 * HWDIM + colb));

    #pragma unroll 2
    for (int it = 0; it < 16; it++) {
        const int h = h0 + it;
        float4 rp = (h < HWDIM - 1)
            ? __ldg(reinterpret_cast<const float4*>(xp + (h + 1) * HWDIM + colb))
            : zero4();

        float4 vi = (DI == 0) ? rm : (DI == 1) ? rc : rp;   // compile-time select
        float4 vj = (DJ == 0) ? rm : (DJ == 1) ? rc : rp;
        vi = hshift(vi, ci, lane);
        vj = hshift(vj, cj, lane);

        float4 pr;
        pr.x = vi.x * vj.x;
        pr.y = vi.y * vj.y;
        pr.z = vi.z * vj.z;
        pr.w = vi.w * vj.w;

        if (TRIPLE) {
            float4 vk = (DK == 0) ? rm : (DK == 1) ? rc : rp;
            vk = hshift(vk, ck, lane);
            pr.x *= vk.x;
            pr.y *= vk.y;
            pr.z *= vk.z;
            pr.w *= vk.w;
        }

        __stcs(reinterpret_cast<float4*>(op + h * HWDIM + colb), pr);
        rm = rc;
        rc = rp;
    }
}

__global__ __launch_bounds__(256)
void high_order_term_kernel(const float* __restrict__ x, float* __restrict__ out)
{
    const int cta = blockIdx.x;           // 0 .. 32*210-1
    const int p   = cta / NTERM;          // plane
    const int t   = cta - p * NTERM;      // term 0..209

    // Arithmetic decode of t -> (i, j[, k]) in the reference enumeration order:
    // t2 = 0..44 (i-major, j>=i); t3 = 45..209 (i-major, j>=i, k>=j).
    int i, j, k = -1;
    if (t < 45) {
        int rem = t, ii = 0;
        while (rem >= 9 - ii) { rem -= 9 - ii; ii++; }
        i = ii; j = ii + rem;
    } else {
        int rem = t - 45, ii = 0;
        for (;;) {
            const int cnt = (9 - ii) * (10 - ii) / 2;   // # of (j,k) pairs for this i
            if (rem < cnt) break;
            rem -= cnt; ii++;
        }
        i = ii;
        int jj = ii;
        while (rem >= 9 - jj) { rem -= 9 - jj; jj++; }
        j = jj; k = jj + rem;
    }

    const int di = i / 3, ci = i % 3;
    const int dj = j / 3, cj = j % 3;
    const int dk = (k >= 0) ? k / 3 : 1;
    const int ck = (k >= 0) ? k % 3 : 1;

    const int lane = threadIdx.x & 31;
    const int warp = threadIdx.x >> 5;

    const float* __restrict__ xp = x + (size_t)p * LPIX;
    float* __restrict__ op = out + ((size_t)p * NTERM + t) * LPIX;

    if (k < 0) {
        // Pairs: di<=dj -> 6 combos.
        switch (di * 3 + dj) {
            case 0: run_term<0, 0, 0, false>(xp, op, ci, cj, ck, lane, warp); break;
            case 1: run_term<0, 1, 0, false>(xp, op, ci, cj, ck, lane, warp); break;
            case 2: run_term<0, 2, 0, false>(xp, op, ci, cj, ck, lane, warp); break;
            case 4: run_term<1, 1, 0, false>(xp, op, ci, cj, ck, lane, warp); break;
            case 5: run_term<1, 2, 0, false>(xp, op, ci, cj, ck, lane, warp); break;
            case 8: run_term<2, 2, 0, false>(xp, op, ci, cj, ck, lane, warp); break;
        }
    } else {
        // Triples: di<=dj<=dk -> 10 combos.
        switch ((di * 3 + dj) * 3 + dk) {
            case  0: run_term<0, 0, 0, true>(xp, op, ci, cj, ck, lane, warp); break;
            case  1: run_term<0, 0, 1, true>(xp, op, ci, cj, ck, lane, warp); break;
            case  2: run_term<0, 0, 2, true>(xp, op, ci, cj, ck, lane, warp); break;
            case  4: run_term<0, 1, 1, true>(xp, op, ci, cj, ck, lane, warp); break;
            case  5: run_term<0, 1, 2, true>(xp, op, ci, cj, ck, lane, warp); break;
            case  8: run_term<0, 2, 2, true>(xp, op, ci, cj, ck, lane, warp); break;
            case 13: run_term<1, 1, 1, true>(xp, op, ci, cj, ck, lane, warp); break;
            case 14: run_term<1, 1, 2, true>(xp, op, ci, cj, ck, lane, warp); break;
            case 17: run_term<1, 2, 2, true>(xp, op, ci, cj, ck, lane, warp); break;
            case 26: run_term<2, 2, 2, true>(xp, op, ci, cj, ck, lane, warp); break;
        }
    }
}

extern "C" void kernel_launch(void* const* d_in, const int* in_sizes, int n_in,
                              void* d_out, int out_size)
{
    const float* x = (const float*)d_in[0];
    float* out = (float*)d_out;
    // tpcm2 (d_in[1]) / tpcm3 (d_in[2]) are compile-time constants for K=3; hardcoded.
    (void)in_sizes; (void)n_in; (void)out_size;

    const int grid = 32 * NTERM;   // one CTA per (plane, term) = 6720
    const int block = 256;         // 8 warps x 16 rows, lane covers one float4
    high_order_term_kernel<<<grid, block>>>(x, out);
}